// round 4
// baseline (speedup 1.0000x reference)
#include <cuda_runtime.h>
#include <math.h>

// ---------------------------------------------------------------------------
// ConvolutionDMax: per-segment valid conv (w=1,2,3, C=M=128) + ReLU + ragged
// segment max + linear(384->128) + tanh.  Packed-f32x2 (FFMA2) main loop.
//
// Inputs (metadata order):
//  0: x       [total,128] f32
//  1: sizes   [batch]     i32
//  2: conv_w0 [128,128,1] f32   3: conv_b0 [128]
//  4: conv_w1 [128,128,2] f32   5: conv_b1 [128]
//  6: conv_w2 [128,128,3] f32   7: conv_b2 [128]
//  8: lin_w   [128,384]   f32   9: lin_b   [128]
// Output: [batch,128] f32
// ---------------------------------------------------------------------------

#define CDIM 128
#define MDIM 128
#define MAX_BATCH 8192
#define XS_ROWS 66        // max t read = t0max(56) + 9 = 65
#define XST 66            // smem time-stride: even (8B pair alignment), 4*66%32=8 -> 8-way not 16-way
#define TT 8              // time-steps per register tile

typedef unsigned long long u64;

// Scratch (no allocations allowed anywhere)
__device__ int   g_off[MAX_BATCH + 1];
// Packed duplicated conv weights: [c][g][m] float4, g=0:(w1,w1,w2a,w2a)
// g=1:(w2b,w2b,w3a,w3a)  g=2:(w3b,w3b,w3c,w3c)
__device__ float4 g_W4[CDIM * 3 * MDIM];
__device__ float g_bias[3 * MDIM];
__device__ float g_lwt[384 * MDIM];          // [k][m]
__device__ float g_pooled[MAX_BATCH * 384];

// ---- f32x2 helpers --------------------------------------------------------
__device__ __forceinline__ u64 fma2(u64 a, u64 b, u64 c) {
    u64 d;
    asm("fma.rn.f32x2 %0, %1, %2, %3;" : "=l"(d) : "l"(a), "l"(b), "l"(c));
    return d;
}
__device__ __forceinline__ void unpack2(u64 v, float& lo, float& hi) {
    asm("mov.b64 {%0, %1}, %2;" : "=f"(lo), "=f"(hi) : "l"(v));
}
struct U64x2 { u64 a, b; };
union F4U { float4 f; U64x2 u; };

// ---------------------------------------------------------------------------
// Kernel 0: exclusive scan of sizes -> g_off
// ---------------------------------------------------------------------------
__global__ void scan_kernel(const int* __restrict__ sizes, int batch) {
    __shared__ int part[256];
    const int tid = threadIdx.x;
    const int chunk = (batch + 255) / 256;
    const int begin = tid * chunk;
    const int end = min(begin + chunk, batch);
    int sum = 0;
    for (int i = begin; i < end; ++i) sum += sizes[i];
    part[tid] = sum;
    __syncthreads();
    if (tid == 0) {
        int run = 0;
        for (int j = 0; j < 256; ++j) { int v = part[j]; part[j] = run; run += v; }
        g_off[batch] = run;
    }
    __syncthreads();
    int run = part[tid];
    for (int i = begin; i < end; ++i) { g_off[i] = run; run += sizes[i]; }
}

// ---------------------------------------------------------------------------
// Kernel 1: pack weights (duplicated pairs) + transposed linear weights.
// ---------------------------------------------------------------------------
__global__ void pack_kernel(const float* __restrict__ w0, const float* __restrict__ b0,
                            const float* __restrict__ w1, const float* __restrict__ b1,
                            const float* __restrict__ w2, const float* __restrict__ b2,
                            const float* __restrict__ lw) {
    int idx = blockIdx.x * blockDim.x + threadIdx.x;
    if (idx < CDIM * MDIM) {
        int c = idx / MDIM, m = idx % MDIM;
        float v1  = w0[m * 128 + c];                 // [M,C,1]
        float v2a = w1[(m * 128 + c) * 2 + 0];       // [M,C,2]
        float v2b = w1[(m * 128 + c) * 2 + 1];
        float v3a = w2[(m * 128 + c) * 3 + 0];       // [M,C,3]
        float v3b = w2[(m * 128 + c) * 3 + 1];
        float v3c = w2[(m * 128 + c) * 3 + 2];
        g_W4[(c * 3 + 0) * MDIM + m] = make_float4(v1, v1, v2a, v2a);
        g_W4[(c * 3 + 1) * MDIM + m] = make_float4(v2b, v2b, v3a, v3a);
        g_W4[(c * 3 + 2) * MDIM + m] = make_float4(v3b, v3b, v3c, v3c);
    } else if (idx < CDIM * MDIM + 384 * 128) {
        int r = idx - CDIM * MDIM;
        int k = r / 128, m = r % 128;
        g_lwt[r] = lw[m * 384 + k];
    } else if (idx < CDIM * MDIM + 384 * 128 + 384) {
        int r = idx - (CDIM * MDIM + 384 * 128);
        g_bias[r] = (r < 128) ? b0[r] : (r < 256) ? b1[r - 128] : b2[r - 256];
    }
}

// ---------------------------------------------------------------------------
// Kernel 2: per-segment conv + ReLU + max, packed f32x2 register tile.
// One CTA per segment, 128 threads (thread = output channel m).
// x tile transposed in smem ([c][t]); all taps fed by EVEN-aligned pairs.
// ---------------------------------------------------------------------------
__global__ void __launch_bounds__(128) conv_dmax_kernel(const float* __restrict__ x, int batch) {
    const int i = blockIdx.x;
    if (i >= batch) return;
    const int off = g_off[i];
    const int s = g_off[i + 1] - off;

    __shared__ __align__(16) float xs[CDIM * XST];   // 33.8 KB, [c][t]

    const int tid = threadIdx.x;
    // Transposed load: x[row][c] -> xs[c][row]; rows >= s zero-padded.
    {
        const float4* xsrc = (const float4*)(x + (size_t)off * CDIM);
        for (int idx = tid; idx < XS_ROWS * 32; idx += 128) {
            const int row = idx >> 5;
            const int c0 = (idx & 31) << 2;
            float4 v = (row < s) ? xsrc[idx] : make_float4(0.f, 0.f, 0.f, 0.f);
            xs[(c0 + 0) * XST + row] = v.x;
            xs[(c0 + 1) * XST + row] = v.y;
            xs[(c0 + 2) * XST + row] = v.z;
            xs[(c0 + 3) * XST + row] = v.w;
        }
    }
    __syncthreads();

    const int m = tid;
    const float b1 = g_bias[m];
    const float b2 = g_bias[128 + m];
    const float b3 = g_bias[256 + m];
    const float4* __restrict__ Wm = g_W4 + m;

    float pm1 = 0.f, pm2 = 0.f, pm3 = 0.f;  // ReLU outputs are >= 0

    for (int t0 = 0; t0 < s; t0 += TT) {
        // Shifted f32x2 accumulators (bias added in epilogue).
        u64 A1[4] = {0, 0, 0, 0};
        u64 A2[4] = {0, 0, 0, 0};
        u64 B2[5] = {0, 0, 0, 0, 0};
        u64 A3[4] = {0, 0, 0, 0};
        u64 B3[5] = {0, 0, 0, 0, 0};
        u64 C3[5] = {0, 0, 0, 0, 0};

#pragma unroll 1
        for (int c = 0; c < CDIM; ++c) {
            F4U wA, wB, wC;
            wA.f = Wm[(c * 3 + 0) * MDIM];
            wB.f = Wm[(c * 3 + 1) * MDIM];
            wC.f = Wm[(c * 3 + 2) * MDIM];
            const u64 w1p  = wA.u.a, w2ap = wA.u.b;
            const u64 w2bp = wB.u.a, w3ap = wB.u.b;
            const u64 w3bp = wC.u.a, w3cp = wC.u.b;

            const float* xc = xs + c * XST + t0;   // 8B-aligned (XST, t0 even)
            u64 P[5];
#pragma unroll
            for (int k = 0; k < 5; ++k)
                P[k] = *(const u64*)(xc + 2 * k);  // broadcast LDS.64

#pragma unroll
            for (int j = 0; j < 4; ++j) {
                A1[j] = fma2(w1p,  P[j], A1[j]);
                A2[j] = fma2(w2ap, P[j], A2[j]);
                A3[j] = fma2(w3ap, P[j], A3[j]);
            }
#pragma unroll
            for (int k = 0; k < 5; ++k) {
                B2[k] = fma2(w2bp, P[k], B2[k]);
                B3[k] = fma2(w3bp, P[k], B3[k]);
                C3[k] = fma2(w3cp, P[k], C3[k]);
            }
        }

        // Recombine shifted halves -> scalar outputs, ReLU + masked max.
        float a1l[4], a1h[4], a2l[4], a2h[4], a3l[4], a3h[4];
        float b2l[5], b2h[5], b3l[5], b3h[5], c3l[5], c3h[5];
#pragma unroll
        for (int j = 0; j < 4; ++j) {
            unpack2(A1[j], a1l[j], a1h[j]);
            unpack2(A2[j], a2l[j], a2h[j]);
            unpack2(A3[j], a3l[j], a3h[j]);
        }
#pragma unroll
        for (int k = 0; k < 5; ++k) {
            unpack2(B2[k], b2l[k], b2h[k]);
            unpack2(B3[k], b3l[k], b3h[k]);
            unpack2(C3[k], c3l[k], c3h[k]);
        }
#pragma unroll
        for (int j = 0; j < 4; ++j) {
            const int te = t0 + 2 * j;
            const float y1e = a1l[j] + b1;
            const float y1o = a1h[j] + b1;
            const float y2e = a2l[j] + b2h[j] + b2;
            const float y2o = a2h[j] + b2l[j + 1] + b2;
            const float y3e = a3l[j] + b3h[j] + c3l[j + 1] + b3;
            const float y3o = a3h[j] + b3l[j + 1] + c3h[j + 1] + b3;
            if (te < s)         pm1 = fmaxf(pm1, fmaxf(y1e, 0.f));
            if (te + 1 < s)     pm1 = fmaxf(pm1, fmaxf(y1o, 0.f));
            if (te < s - 1)     pm2 = fmaxf(pm2, fmaxf(y2e, 0.f));
            if (te + 1 < s - 1) pm2 = fmaxf(pm2, fmaxf(y2o, 0.f));
            if (te < s - 2)     pm3 = fmaxf(pm3, fmaxf(y3e, 0.f));
            if (te + 1 < s - 2) pm3 = fmaxf(pm3, fmaxf(y3o, 0.f));
        }
    }

    float* p = g_pooled + (size_t)i * 384;
    p[m] = pm1;
    p[128 + m] = pm2;
    p[256 + m] = pm3;
}

// ---------------------------------------------------------------------------
// Kernel 3: out = tanh(pooled @ lin_w^T + lin_b). 16 segments per CTA.
// ---------------------------------------------------------------------------
#define GSEG 16
__global__ void __launch_bounds__(128) linear_kernel(const float* __restrict__ lin_b,
                                                     float* __restrict__ out, int batch) {
    __shared__ float ps[GSEG * 384];   // 24 KB
    const int base = blockIdx.x * GSEG;
    const int tid = threadIdx.x;
    const int navail = min(GSEG, batch - base);
    if (navail <= 0) return;

    for (int idx = tid; idx < navail * 384; idx += 128)
        ps[idx] = g_pooled[(size_t)base * 384 + idx];
    __syncthreads();

    const int m = tid;
    const float lb = lin_b[m];
    float acc[GSEG];
#pragma unroll
    for (int g = 0; g < GSEG; ++g) acc[g] = lb;

    for (int k = 0; k < 384; ++k) {
        const float wv = g_lwt[k * 128 + m];
#pragma unroll
        for (int g = 0; g < GSEG; ++g)
            acc[g] += wv * ps[g * 384 + k];
    }
#pragma unroll
    for (int g = 0; g < GSEG; ++g)
        if (g < navail)
            out[(size_t)(base + g) * MDIM + m] = tanhf(acc[g]);
}

// ---------------------------------------------------------------------------
extern "C" void kernel_launch(void* const* d_in, const int* in_sizes, int n_in,
                              void* d_out, int out_size) {
    const float* x  = (const float*)d_in[0];
    const int* sizes = (const int*)d_in[1];
    const float* w0 = (const float*)d_in[2];
    const float* b0 = (const float*)d_in[3];
    const float* w1 = (const float*)d_in[4];
    const float* b1 = (const float*)d_in[5];
    const float* w2 = (const float*)d_in[6];
    const float* b2 = (const float*)d_in[7];
    const float* lw = (const float*)d_in[8];
    const float* lb = (const float*)d_in[9];
    float* out = (float*)d_out;

    const int batch = in_sizes[1];

    scan_kernel<<<1, 256>>>(sizes, batch);

    const int pack_elems = CDIM * MDIM + 384 * 128 + 384;
    pack_kernel<<<(pack_elems + 255) / 256, 256>>>(w0, b0, w1, b1, w2, b2, lw);

    conv_dmax_kernel<<<batch, 128>>>(x, batch);

    linear_kernel<<<(batch + GSEG - 1) / GSEG, 128>>>(lb, out, batch);
}

// round 16
// speedup vs baseline: 1.2232x; 1.2232x over previous
#include <cuda_runtime.h>
#include <cuda_bf16.h>
#include <mma.h>
#include <math.h>

using namespace nvcuda;

// ---------------------------------------------------------------------------
// ConvolutionDMax via WMMA bf16 split-precision GEMM (sm_103 base target —
// tcgen05 is unavailable in this harness, HMMA path instead).
// y_all[t] (384 cols: y1|y2|y3) = sum_j x[t+j] . W_j   (flat stream, j=0..2)
// Precision: x,W split to bf16 hi+lo; D += Ahi*Whi + Alo*Whi + Ahi*Wlo (fp32).
// Epilogue: +bias, ReLU, ragged segment max. Then linear 384->128 + tanh.
// ---------------------------------------------------------------------------

#define MAX_BATCH 8192
#define MAX_TOTAL (8192 * 63)          // sizes in [16,63]
#define MAXR (MAX_TOTAL + 192)         // padded rows for halo
#define TILE_OUT 126                   // output rows per tile (2-row halo)
#define MAX_TILES ((MAX_TOTAL + TILE_OUT - 1) / TILE_OUT)   // 4097

#define AST 144                        // A smem stride (bf16) = 288B (32B mult)
#define BST 144                        // B smem stride (bf16)
#define CST 136                        // C smem stride (fp32) = 544B (32B mult)

#define SM_AHI 0
#define SM_ALO (132 * AST * 2)                 // 38016
#define SM_BC  (2 * 132 * AST * 2)             // 76032 (B and C share region)
#define SM_MAX (SM_BC + 128 * CST * 4)         // 76032 + 69632 = 145664
#define SM_TOT (SM_MAX + 9 * 384 * 4 + 64)     // ~159.5 KB

typedef unsigned int u32;

// ---- device scratch (no allocations anywhere) -----------------------------
__device__ int   g_off[MAX_BATCH + 1];
__device__ int   g_segid[MAXR];
__device__ __align__(256) __nv_bfloat16 g_xhi[(size_t)MAXR * 128];
__device__ __align__(256) __nv_bfloat16 g_xlo[(size_t)MAXR * 128];
__device__ __align__(256) __nv_bfloat16 g_Bpk[12 * 128 * 128]; // [q][n][k]
__device__ float g_bias[384];
__device__ float g_lwt[384 * 128];             // [k][m]
__device__ float g_pooled[MAX_BATCH * 384];

// chunk tables: q = 0..11  (j = shift, prec = 0:hi 1:lo, NST = N col start)
__device__ const int Q_J[12]    = {0,0,0,0,0,0, 1,1,1,1, 2,2};
__device__ const int Q_PREC[12] = {0,0,0,1,1,1, 0,0,1,1, 0,1};
__device__ const int Q_NST[12]  = {0,128,256, 0,128,256, 128,256, 128,256, 256,256};

// ---------------------------------------------------------------------------
// Kernel 0: exclusive scan of sizes -> g_off
// ---------------------------------------------------------------------------
__global__ void scan_kernel(const int* __restrict__ sizes, int batch) {
    __shared__ int part[256];
    const int tid = threadIdx.x;
    const int chunk = (batch + 255) / 256;
    const int begin = tid * chunk, end = min(begin + chunk, batch);
    int sum = 0;
    for (int i = begin; i < end; ++i) sum += sizes[i];
    part[tid] = sum;
    __syncthreads();
    if (tid == 0) {
        int run = 0;
        for (int j = 0; j < 256; ++j) { int v = part[j]; part[j] = run; run += v; }
        g_off[batch] = run;
    }
    __syncthreads();
    int run = part[tid];
    for (int i = begin; i < end; ++i) { g_off[i] = run; run += sizes[i]; }
}

// ---------------------------------------------------------------------------
// Kernel 1: pack B chunks [q][n][k] (hi/lo), lin_w^T, bias.
// ---------------------------------------------------------------------------
__global__ void pack_kernel(const float* __restrict__ w0, const float* __restrict__ b0,
                            const float* __restrict__ w1, const float* __restrict__ b1,
                            const float* __restrict__ w2, const float* __restrict__ b2,
                            const float* __restrict__ lw) {
    int idx = blockIdx.x * blockDim.x + threadIdx.x;
    if (idx < 12 * 16384) {
        int q = idx / 16384, r = idx % 16384;
        int n_l = r / 128, k = r % 128;
        int j = Q_J[q], prec = Q_PREC[q], n = Q_NST[q] + n_l;
        float v;
        if (n < 128)      v = w0[n * 128 + k];
        else if (n < 256) v = w1[((n - 128) * 128 + k) * 2 + j];
        else              v = w2[((n - 256) * 128 + k) * 3 + j];
        __nv_bfloat16 h = __float2bfloat16(v);
        __nv_bfloat16 o = prec ? __float2bfloat16(v - __bfloat162float(h)) : h;
        g_Bpk[idx] = o;
    } else if (idx < 12 * 16384 + 384 * 128) {
        int r = idx - 12 * 16384;
        int k = r / 128, m = r % 128;
        g_lwt[r] = lw[m * 384 + k];
    } else if (idx < 12 * 16384 + 384 * 128 + 384) {
        int r = idx - (12 * 16384 + 384 * 128);
        g_bias[r] = (r < 128) ? b0[r] : (r < 256) ? b1[r - 128] : b2[r - 256];
    }
}

// ---------------------------------------------------------------------------
// Kernel 2: x -> bf16 hi/lo, zero-padded halo rows.
// ---------------------------------------------------------------------------
__global__ void xprep_kernel(const float* __restrict__ x, int batch) {
    const int total = g_off[batch];
    long gid = (long)blockIdx.x * blockDim.x + threadIdx.x;
    int row = (int)(gid >> 5);
    if (row >= MAXR || row >= total + 192) return;
    int c4 = (int)(gid & 31) * 4;
    float4 v = make_float4(0.f, 0.f, 0.f, 0.f);
    if (row < total) v = ((const float4*)x)[(size_t)row * 32 + (gid & 31)];
    __nv_bfloat16 h0 = __float2bfloat16(v.x), h1 = __float2bfloat16(v.y);
    __nv_bfloat16 h2 = __float2bfloat16(v.z), h3 = __float2bfloat16(v.w);
    __nv_bfloat16 l0 = __float2bfloat16(v.x - __bfloat162float(h0));
    __nv_bfloat16 l1 = __float2bfloat16(v.y - __bfloat162float(h1));
    __nv_bfloat16 l2 = __float2bfloat16(v.z - __bfloat162float(h2));
    __nv_bfloat16 l3 = __float2bfloat16(v.w - __bfloat162float(h3));
    uint2 ph, pl;
    ph.x = ((u32)__bfloat16_as_ushort(h1) << 16) | __bfloat16_as_ushort(h0);
    ph.y = ((u32)__bfloat16_as_ushort(h3) << 16) | __bfloat16_as_ushort(h2);
    pl.x = ((u32)__bfloat16_as_ushort(l1) << 16) | __bfloat16_as_ushort(l0);
    pl.y = ((u32)__bfloat16_as_ushort(l3) << 16) | __bfloat16_as_ushort(l2);
    *(uint2*)(g_xhi + (size_t)row * 128 + c4) = ph;
    *(uint2*)(g_xlo + (size_t)row * 128 + c4) = pl;
}

// ---------------------------------------------------------------------------
// Kernel 3: segment ids + zero pooled (every launch — graph replay safe).
// ---------------------------------------------------------------------------
__global__ void segid_kernel(int batch) {
    const int i = blockIdx.x;
    const int off = g_off[i], s = g_off[i + 1] - off;
    for (int t = threadIdx.x; t < s; t += 128) g_segid[off + t] = i;
    for (int c = threadIdx.x; c < 384; c += 128) g_pooled[(size_t)i * 384 + c] = 0.f;
}

// ---------------------------------------------------------------------------
// Kernel 4: WMMA GEMM conv + epilogue segmented max.
// 256 threads, warp grid 4(M)x2(N); per slice C = 128x128 fp32 in fragments.
// ---------------------------------------------------------------------------
__global__ void __launch_bounds__(256, 1)
conv_gemm_kernel(int batch) {
    extern __shared__ __align__(128) char sm[];
    const int total = g_off[batch];
    const int t0 = blockIdx.x * TILE_OUT;
    if (t0 >= total) return;

    const int tid = threadIdx.x;
    const int wid = tid >> 5;
    const int wm = wid & 3, wn = wid >> 2;

    __nv_bfloat16* Ah = (__nv_bfloat16*)(sm + SM_AHI);
    __nv_bfloat16* Al = (__nv_bfloat16*)(sm + SM_ALO);
    __nv_bfloat16* Bs = (__nv_bfloat16*)(sm + SM_BC);
    float* Cs = (float*)(sm + SM_BC);
    float* smax = (float*)(sm + SM_MAX);

    // Stage A (132 rows: 126 out + halo) hi/lo with padded stride.
    for (int idx = tid; idx < 132 * 16; idx += 256) {
        int r = idx >> 4, v = idx & 15;
        uint4 h = *(const uint4*)(g_xhi + (size_t)(t0 + r) * 128 + v * 8);
        uint4 l = *(const uint4*)(g_xlo + (size_t)(t0 + r) * 128 + v * 8);
        *(uint4*)(Ah + r * AST + v * 8) = h;
        *(uint4*)(Al + r * AST + v * 8) = l;
    }
    for (int idx = tid; idx < 9 * 384; idx += 256) smax[idx] = 0.f;
    __syncthreads();

    const int QHI[3] = {0, 6, 10};
    const int QLO[3] = {3, 8, 11};

    for (int s = 0; s < 3; ++s) {
        wmma::fragment<wmma::accumulator, 16, 16, 16, float> acc[2][4];
#pragma unroll
        for (int mi = 0; mi < 2; ++mi)
#pragma unroll
            for (int ni = 0; ni < 4; ++ni) wmma::fill_fragment(acc[mi][ni], 0.f);

        for (int j = 0; j <= s; ++j) {
            for (int grp = 0; grp < 2; ++grp) {        // grp0: Whi (Ahi+Alo); grp1: Wlo (Ahi)
                const int q = (grp ? QLO[j] : QHI[j]) + (s - j);
                __syncthreads();
                for (int idx = tid; idx < 128 * 16; idx += 256) {
                    int n = idx >> 4, v = idx & 15;
                    *(uint4*)(Bs + n * BST + v * 8) =
                        *(const uint4*)(g_Bpk + q * 16384 + n * 128 + v * 8);
                }
                __syncthreads();
                const int npass = grp ? 1 : 2;
                for (int p = 0; p < npass; ++p) {
                    const __nv_bfloat16* Ab = (grp == 0 && p == 1) ? Al : Ah;
                    const __nv_bfloat16* Arow = Ab + (wm * 32 + j) * AST;
#pragma unroll
                    for (int k = 0; k < 8; ++k) {
                        wmma::fragment<wmma::matrix_a, 16, 16, 16, __nv_bfloat16, wmma::row_major> af[2];
                        wmma::fragment<wmma::matrix_b, 16, 16, 16, __nv_bfloat16, wmma::col_major> bf[4];
                        wmma::load_matrix_sync(af[0], Arow + k * 16, AST);
                        wmma::load_matrix_sync(af[1], Arow + 16 * AST + k * 16, AST);
#pragma unroll
                        for (int ni = 0; ni < 4; ++ni)
                            wmma::load_matrix_sync(bf[ni], Bs + (wn * 64 + ni * 16) * BST + k * 16, BST);
#pragma unroll
                        for (int mi = 0; mi < 2; ++mi)
#pragma unroll
                            for (int ni = 0; ni < 4; ++ni)
                                wmma::mma_sync(acc[mi][ni], af[mi], bf[ni], acc[mi][ni]);
                    }
                }
            }
        }
        __syncthreads();   // B finished for this slice; reuse region as C
#pragma unroll
        for (int mi = 0; mi < 2; ++mi)
#pragma unroll
            for (int ni = 0; ni < 4; ++ni)
                wmma::store_matrix_sync(Cs + (wm * 32 + mi * 16) * CST + wn * 64 + ni * 16,
                                        acc[mi][ni], CST, wmma::mem_row_major);
        __syncthreads();

        // epilogue slice s: bias + relu + masked segmented max
        {
            const int r = tid >> 1, coff = (tid & 1) * 64;
            const int t = t0 + r;
            if (r < TILE_OUT && t < total) {
                const int seg = g_segid[t];
                const int segl = seg - g_segid[t0];
                const int cum = g_off[seg + 1];
                if (t + s < cum) {
#pragma unroll 8
                    for (int c = 0; c < 64; ++c) {
                        float v = Cs[r * CST + coff + c] + g_bias[s * 128 + coff + c];
                        v = fmaxf(v, 0.f);
                        atomicMax((int*)&smax[segl * 384 + s * 128 + coff + c], __float_as_int(v));
                    }
                }
            }
        }
        __syncthreads();
    }

    // flush smax -> g_pooled
    const int seg0 = g_segid[t0];
    const int tlast = min(t0 + TILE_OUT - 1, total - 1);
    const int nseg = g_segid[tlast] - seg0 + 1;
    for (int idx = tid; idx < nseg * 384; idx += 256) {
        int sl = idx / 384, c = idx - sl * 384;
        atomicMax((int*)&g_pooled[(size_t)(seg0 + sl) * 384 + c], __float_as_int(smax[idx]));
    }
}

// ---------------------------------------------------------------------------
// Kernel 5: out = tanh(pooled @ lin_w^T + lin_b). 24 segments per CTA.
// ---------------------------------------------------------------------------
#define GSEG 24
__global__ void __launch_bounds__(128) linear_kernel(const float* __restrict__ lin_b,
                                                     float* __restrict__ out, int batch) {
    __shared__ float ps[GSEG * 384];
    const int base = blockIdx.x * GSEG;
    const int tid = threadIdx.x;
    const int navail = min(GSEG, batch - base);
    if (navail <= 0) return;
    for (int idx = tid; idx < navail * 384; idx += 128)
        ps[idx] = g_pooled[(size_t)base * 384 + idx];
    __syncthreads();
    const int m = tid;
    const float lb = lin_b[m];
    float acc[GSEG];
#pragma unroll
    for (int g = 0; g < GSEG; ++g) acc[g] = lb;
    for (int k = 0; k < 384; ++k) {
        const float wv = g_lwt[k * 128 + m];
#pragma unroll
        for (int g = 0; g < GSEG; ++g) acc[g] += wv * ps[g * 384 + k];
    }
#pragma unroll
    for (int g = 0; g < GSEG; ++g)
        if (g < navail) out[(size_t)(base + g) * 128 + m] = tanhf(acc[g]);
}

// ---------------------------------------------------------------------------
extern "C" void kernel_launch(void* const* d_in, const int* in_sizes, int n_in,
                              void* d_out, int out_size) {
    const float* x  = (const float*)d_in[0];
    const int* sizes = (const int*)d_in[1];
    const float* w0 = (const float*)d_in[2];
    const float* b0 = (const float*)d_in[3];
    const float* w1 = (const float*)d_in[4];
    const float* b1 = (const float*)d_in[5];
    const float* w2 = (const float*)d_in[6];
    const float* b2 = (const float*)d_in[7];
    const float* lw = (const float*)d_in[8];
    const float* lb = (const float*)d_in[9];
    float* out = (float*)d_out;
    const int batch = in_sizes[1];

    cudaFuncSetAttribute(conv_gemm_kernel,
                         cudaFuncAttributeMaxDynamicSharedMemorySize, SM_TOT);

    scan_kernel<<<1, 256>>>(sizes, batch);

    const int pack_elems = 12 * 16384 + 384 * 128 + 384;
    pack_kernel<<<(pack_elems + 255) / 256, 256>>>(w0, b0, w1, b1, w2, b2, lw);

    const long xp_threads = (long)MAXR * 32;
    xprep_kernel<<<(int)((xp_threads + 255) / 256), 256>>>(x, batch);

    segid_kernel<<<batch, 128>>>(batch);

    conv_gemm_kernel<<<MAX_TILES, 256, SM_TOT>>>(batch);

    linear_kernel<<<(batch + GSEG - 1) / GSEG, 128>>>(lb, out, batch);
}